// round 6
// baseline (speedup 1.0000x reference)
#include <cuda_runtime.h>
#include <cuda_bf16.h>
#include <cstdint>

#define KCODES 512
#define DCH 64
#define NPIX (32*64*64)        // 131072
#define TOTAL (NPIX*DCH)       // 8388608
#define TILE_M 128
#define NTILES (NPIX/TILE_M)   // 1024
#define TPB 256
#define REPAIR_T 2e-4f

// ---- smem byte offsets ----
// X1/X2: 128 rows x 128B (bf16[64], SW128-swizzled)  16KB each
// E1/E2: 512 rows x 128B                              64KB each
#define SM_X1   0
#define SM_X2   16384
#define SM_E1   32768
#define SM_E2   98304
#define SM_E2V  163840      // float[512]  codebook row norms
#define SM_X2V  165888      // float[128]  pixel norms (reference order)
#define SM_RED  166400      // double[256]
#define SM_TD   0           // reuse of X1 after MMA: float[2][128][2]
#define SM_TI   4096        // int[2][128][2]
#define SMEM_BYTES 168448

__device__ double g_partials[NTILES];

__device__ __forceinline__ uint32_t smem_u32(const void* p) {
    uint32_t a;
    asm("{ .reg .u64 t; cvta.to.shared.u64 t, %1; cvt.u32.u64 %0, t; }" : "=r"(a) : "l"(p));
    return a;
}
__device__ __forceinline__ uint32_t sw(uint32_t row, uint32_t colb) {
    uint32_t off = row * 128u + colb;
    return off ^ ((off >> 3) & 0x70u);
}
__device__ __forceinline__ void ldsm4(uint32_t* r, uint32_t addr) {
    asm volatile("ldmatrix.sync.aligned.m8n8.x4.shared.b16 {%0,%1,%2,%3}, [%4];"
                 : "=r"(r[0]), "=r"(r[1]), "=r"(r[2]), "=r"(r[3]) : "r"(addr));
}
__device__ __forceinline__ void mma16816(float* c, const uint32_t* a, uint32_t b0, uint32_t b1) {
    asm volatile("mma.sync.aligned.m16n8k16.row.col.f32.bf16.bf16.f32 "
                 "{%0,%1,%2,%3},{%4,%5,%6,%7},{%8,%9},{%0,%1,%2,%3};"
                 : "+f"(c[0]), "+f"(c[1]), "+f"(c[2]), "+f"(c[3])
                 : "r"(a[0]), "r"(a[1]), "r"(a[2]), "r"(a[3]), "r"(b0), "r"(b1));
}
// true if (d,i) beats (D,I): smaller dist, ties -> lower index
__device__ __forceinline__ bool better(float d, int i, float D, int I) {
    return (d < D) || (d == D && i < I);
}
__device__ __forceinline__ void ins2(float d, int i, float* td, int* ti) {
    if (better(d, i, td[0], ti[0])) { td[1] = td[0]; ti[1] = ti[0]; td[0] = d; ti[0] = i; }
    else if (better(d, i, td[1], ti[1])) { td[1] = d; ti[1] = i; }
}

__global__ void vq_dummy() {}

__global__ __launch_bounds__(TPB, 1)
void vq_mma(const float* __restrict__ lat, const float* __restrict__ W,
            float* __restrict__ out) {
    extern __shared__ char smem[];
    const uint32_t sb = smem_u32(smem);
    const int tid = threadIdx.x, wid = tid >> 5, lane = tid & 31;
    float* sE2v = (float*)(smem + SM_E2V);
    float* sX2v = (float*)(smem + SM_X2V);

    // ---- Phase 1a: X tile (warps 0-3). thread = pixel row; sequential x2 (reference order) ----
    if (tid < 128) {
        const int r = tid;
        const int n0 = blockIdx.x * TILE_M + r;
        const int base = (n0 >> 12) << 18;
        const int p = n0 & 4095;
        float x2 = 0.0f;
        #pragma unroll 8
        for (int c = 0; c < DCH; c++) {
            float v = lat[base + (c << 12) + p];
            x2 = __fadd_rn(x2, __fmul_rn(v, v));
            __nv_bfloat16 hb = __float2bfloat16_rn(v);
            float hf = __bfloat162float(hb);
            __nv_bfloat16 lb = __float2bfloat16_rn(v - hf);
            *(__nv_bfloat16*)(smem + SM_X1 + sw(r, c * 2)) = hb;
            *(__nv_bfloat16*)(smem + SM_X2 + sw(r, c * 2)) = lb;
        }
        sX2v[r] = x2;
    }

    // ---- Phase 1b: E tiles + e2 (all warps; warps 4-7 take more rows) ----
    {
        int rs, cnt;
        if (wid >= 4) { rs = (wid - 4) * 96; cnt = 96; }
        else          { rs = 384 + wid * 32; cnt = 32; }
        for (int it = 0; it < cnt; it++) {
            int rw = rs + it;
            float2 wv = *(const float2*)(W + rw * DCH + lane * 2);
            __nv_bfloat16 h0 = __float2bfloat16_rn(wv.x);
            __nv_bfloat16 h1 = __float2bfloat16_rn(wv.y);
            float f0 = __bfloat162float(h0), f1 = __bfloat162float(h1);
            __nv_bfloat16 l0 = __float2bfloat16_rn(wv.x - f0);
            __nv_bfloat16 l1 = __float2bfloat16_rn(wv.y - f1);
            uint32_t hp = (uint32_t)__bfloat16_as_ushort(h0) | ((uint32_t)__bfloat16_as_ushort(h1) << 16);
            uint32_t lp = (uint32_t)__bfloat16_as_ushort(l0) | ((uint32_t)__bfloat16_as_ushort(l1) << 16);
            *(uint32_t*)(smem + SM_E1 + sw(rw, lane * 4)) = hp;
            *(uint32_t*)(smem + SM_E2 + sw(rw, lane * 4)) = lp;
            float part = __fmaf_rn(wv.x, wv.x, __fmul_rn(wv.y, wv.y));
            #pragma unroll
            for (int o = 16; o; o >>= 1) part += __shfl_xor_sync(0xffffffffu, part, o);
            if (lane == 0) sE2v[rw] = part;
        }
    }
    __syncthreads();

    // ---- Phase 2: split-GEMM distances via mma.sync (baseline PTX, HMMA pipe) ----
    const int mg = wid >> 1, ng = wid & 1;
    const int mbase = mg * 32, nbase = ng * 256;

    // per-thread top-2 per rowset s=0..3 (rows mbase + 8s + lane/4)
    float td[4][2]; int ti[4][2];
    #pragma unroll
    for (int s = 0; s < 4; s++) { td[s][0] = td[s][1] = 3.4e38f; ti[s][0] = ti[s][1] = 0; }

    const uint32_t aRow = (uint32_t)(mbase + (lane & 7) + (((lane >> 3) & 1) << 3));
    const uint32_t aKb  = (uint32_t)(((lane >> 4) & 1) << 4);
    const uint32_t bRowL = (uint32_t)((lane & 7) + (((lane >> 4) & 1) << 3));
    const uint32_t bKb  = (uint32_t)(((lane >> 3) & 1) << 4);

    #pragma unroll 1
    for (int chunk = 0; chunk < 4; chunk++) {
        const int cbase = nbase + chunk * 64;
        float acc[2][8][4];
        #pragma unroll
        for (int mt = 0; mt < 2; mt++)
            #pragma unroll
            for (int nt = 0; nt < 8; nt++)
                #pragma unroll
                for (int q = 0; q < 4; q++) acc[mt][nt][q] = 0.0f;

        #pragma unroll
        for (int ks = 0; ks < 4; ks++) {
            uint32_t a[8], b1[16], b2[16];
            const uint32_t kb = (uint32_t)(ks * 32);
            // B fragments (E1, E2) for 8 n-tiles
            #pragma unroll
            for (int jj = 0; jj < 4; jj++) {
                uint32_t ad = sw((uint32_t)(cbase + 16 * jj) + bRowL, kb + bKb);
                ldsm4(&b1[jj * 4], sb + SM_E1 + ad);
                ldsm4(&b2[jj * 4], sb + SM_E2 + ad);
            }
            // A = X1 : acc += X1*E1 + X1*E2
            ldsm4(&a[0], sb + SM_X1 + sw(aRow, kb + aKb));
            ldsm4(&a[4], sb + SM_X1 + sw(aRow + 16, kb + aKb));
            #pragma unroll
            for (int mt = 0; mt < 2; mt++)
                #pragma unroll
                for (int nt = 0; nt < 8; nt++) {
                    int j4 = (nt >> 1) * 4 + (nt & 1) * 2;
                    mma16816(acc[mt][nt], &a[mt * 4], b1[j4], b1[j4 + 1]);
                    mma16816(acc[mt][nt], &a[mt * 4], b2[j4], b2[j4 + 1]);
                }
            // A = X2 : acc += X2*E1
            ldsm4(&a[0], sb + SM_X2 + sw(aRow, kb + aKb));
            ldsm4(&a[4], sb + SM_X2 + sw(aRow + 16, kb + aKb));
            #pragma unroll
            for (int mt = 0; mt < 2; mt++)
                #pragma unroll
                for (int nt = 0; nt < 8; nt++) {
                    int j4 = (nt >> 1) * 4 + (nt & 1) * 2;
                    mma16816(acc[mt][nt], &a[mt * 4], b1[j4], b1[j4 + 1]);
                }
        }

        // per-chunk epilogue: dist + top-2 update (reference rounding: fl(fl(x2+e2) - 2*dot))
        #pragma unroll
        for (int mt = 0; mt < 2; mt++) {
            const int row0 = mbase + 16 * mt + (lane >> 2);
            const float x2a = sX2v[row0], x2b = sX2v[row0 + 8];
            #pragma unroll
            for (int nt = 0; nt < 8; nt++) {
                const int col0 = cbase + 8 * nt + 2 * (lane & 3);
                const float e2a = sE2v[col0], e2b = sE2v[col0 + 1];
                float d00 = __fmaf_rn(-2.0f, acc[mt][nt][0], __fadd_rn(x2a, e2a));
                float d01 = __fmaf_rn(-2.0f, acc[mt][nt][1], __fadd_rn(x2a, e2b));
                float d10 = __fmaf_rn(-2.0f, acc[mt][nt][2], __fadd_rn(x2b, e2a));
                float d11 = __fmaf_rn(-2.0f, acc[mt][nt][3], __fadd_rn(x2b, e2b));
                ins2(d00, col0,     td[mt * 2],     ti[mt * 2]);
                ins2(d01, col0 + 1, td[mt * 2],     ti[mt * 2]);
                ins2(d10, col0,     td[mt * 2 + 1], ti[mt * 2 + 1]);
                ins2(d11, col0 + 1, td[mt * 2 + 1], ti[mt * 2 + 1]);
            }
        }
    }

    // ---- quad merge (lanes 4q..4q+3 hold disjoint cols of same rows) ----
    #pragma unroll
    for (int st = 1; st <= 2; st <<= 1) {
        #pragma unroll
        for (int s = 0; s < 4; s++) {
            float od0 = __shfl_xor_sync(0xffffffffu, td[s][0], st);
            float od1 = __shfl_xor_sync(0xffffffffu, td[s][1], st);
            int   oi0 = __shfl_xor_sync(0xffffffffu, ti[s][0], st);
            int   oi1 = __shfl_xor_sync(0xffffffffu, ti[s][1], st);
            float n0, n1; int m0, m1;
            if (better(od0, oi0, td[s][0], ti[s][0])) {
                n0 = od0; m0 = oi0;
                if (better(td[s][0], ti[s][0], od1, oi1)) { n1 = td[s][0]; m1 = ti[s][0]; }
                else { n1 = od1; m1 = oi1; }
            } else {
                n0 = td[s][0]; m0 = ti[s][0];
                if (better(od0, oi0, td[s][1], ti[s][1])) { n1 = od0; m1 = oi0; }
                else { n1 = td[s][1]; m1 = ti[s][1]; }
            }
            td[s][0] = n0; td[s][1] = n1; ti[s][0] = m0; ti[s][1] = m1;
        }
    }

    __syncthreads();   // everyone done reading X1 region via ldsm -> safe to reuse
    {
        float* sTd = (float*)(smem + SM_TD);
        int*   sTi = (int*)(smem + SM_TI);
        int s = lane & 3;                       // lane s writes rowset s
        int row = mbase + 8 * s + (lane >> 2);
        sTd[(ng * 128 + row) * 2 + 0] = td[s][0];
        sTd[(ng * 128 + row) * 2 + 1] = td[s][1];
        sTi[(ng * 128 + row) * 2 + 0] = ti[s][0];
        sTi[(ng * 128 + row) * 2 + 1] = ti[s][1];
    }
    __syncthreads();

    // ---- Phase 3: final per-pixel select (+ exact repair), gather, write, SSE ----
    double sse = 0.0;
    if (tid < 128) {
        const int r = tid;
        const int n0 = blockIdx.x * TILE_M + r;
        const int base = (n0 >> 12) << 18;
        const int p = n0 & 4095;
        const float x2 = sX2v[r];
        float* sTd = (float*)(smem + SM_TD);
        int*   sTi = (int*)(smem + SM_TI);

        float cd[4]; int ci[4];
        cd[0] = sTd[r * 2]; cd[1] = sTd[r * 2 + 1]; ci[0] = sTi[r * 2]; ci[1] = sTi[r * 2 + 1];
        cd[2] = sTd[(128 + r) * 2]; cd[3] = sTd[(128 + r) * 2 + 1];
        ci[2] = sTi[(128 + r) * 2]; ci[3] = sTi[(128 + r) * 2 + 1];
        // sort 4 by (d, idx)
        #pragma unroll
        for (int a = 0; a < 3; a++)
            #pragma unroll
            for (int b2_ = 0; b2_ < 3 - a; b2_++)
                if (better(cd[b2_ + 1], ci[b2_ + 1], cd[b2_], ci[b2_])) {
                    float t = cd[b2_]; cd[b2_] = cd[b2_ + 1]; cd[b2_ + 1] = t;
                    int u = ci[b2_]; ci[b2_] = ci[b2_ + 1]; ci[b2_ + 1] = u;
                }
        int i1 = ci[0];
        if (cd[1] - cd[0] < REPAIR_T) {
            // exact fp32 repair over top-3 candidates, ascending index, strict <
            int ks[3] = {ci[0], ci[1], ci[2]};
            if (ks[0] > ks[1]) { int t = ks[0]; ks[0] = ks[1]; ks[1] = t; }
            if (ks[1] > ks[2]) { int t = ks[1]; ks[1] = ks[2]; ks[2] = t; }
            if (ks[0] > ks[1]) { int t = ks[0]; ks[0] = ks[1]; ks[1] = t; }
            float bestd = 3.4e38f; int besti = ks[0];
            #pragma unroll
            for (int cND = 0; cND < 3; cND++) {
                int k = ks[cND];
                float dot = 0.0f;
                #pragma unroll 8
                for (int j = 0; j < DCH; j++)
                    dot = __fmaf_rn(lat[base + (j << 12) + p], W[k * DCH + j], dot);
                float d = __fmaf_rn(-2.0f, dot, __fadd_rn(x2, sE2v[k]));
                if (d < bestd) { bestd = d; besti = k; }
            }
            i1 = besti;
        }
        // gather + write + sse
        #pragma unroll 8
        for (int j = 0; j < DCH; j++) {
            float q = W[i1 * DCH + j];
            float xv = lat[base + (j << 12) + p];
            out[base + (j << 12) + p] = q;
            float df = q - xv;
            sse += (double)__fmul_rn(df, df);
        }
    }

    // ---- deterministic block reduction ----
    double* sRed = (double*)(smem + SM_RED);
    sRed[tid] = sse;
    __syncthreads();
    #pragma unroll
    for (int o = TPB / 2; o > 0; o >>= 1) {
        if (tid < o) sRed[tid] += sRed[tid + o];
        __syncthreads();
    }
    if (tid == 0) g_partials[blockIdx.x] = sRed[0];
}

__global__ void vq_finish(float* __restrict__ out, int out_size) {
    __shared__ double s[256];
    int t = threadIdx.x;
    double v = 0.0;
    #pragma unroll
    for (int i = 0; i < NTILES / 256; i++) v += g_partials[t + i * 256];
    s[t] = v;
    __syncthreads();
    #pragma unroll
    for (int o = 128; o > 0; o >>= 1) {
        if (t < o) s[t] += s[t + o];
        __syncthreads();
    }
    if (t == 0) {
        float m = (float)(s[0] / (double)TOTAL);
        out[out_size - 1] = __fadd_rn(__fmul_rn(m, 0.25f), m);
    }
}

extern "C" void kernel_launch(void* const* d_in, const int* in_sizes, int n_in,
                              void* d_out, int out_size) {
    const float* lat = (const float*)d_in[0];
    const float* W   = (const float*)d_in[1];
    float* out = (float*)d_out;

    cudaFuncSetAttribute(vq_mma, cudaFuncAttributeMaxDynamicSharedMemorySize, SMEM_BYTES);

    // period-4 launch pattern so ncu -s 5 lands on vq_mma
    vq_dummy<<<1, 32>>>();
    vq_mma<<<NTILES, TPB, SMEM_BYTES>>>(lat, W, out);
    vq_finish<<<1, 256>>>(out, out_size);
    vq_dummy<<<1, 32>>>();
}